// round 1
// baseline (speedup 1.0000x reference)
#include <cuda_runtime.h>

#define D 512
#define OUTD 128
#define MAXN 50000
#define MAXE 150000
#define BN_EPS 1e-5f

// ---------------- scratch (static device globals; no allocation) ----------------
__device__ float g_h[(size_t)MAXN * D];     // current node features
__device__ float g_hsum[(size_t)MAXN * D];  // hidden_sum accumulator
__device__ float g_z[(size_t)MAXN * D];     // aggregation buffer / gemm2 output
__device__ float g_y[(size_t)MAXN * D];     // gemm1 output / post-BN1
__device__ float g_s1[(size_t)MAXE * D];    // decoder hidden
__device__ float g_stats[2 * D];            // per-column sum, sumsq
__device__ float g_aff[2 * D];              // per-column scale, shift

// ---------------- embedding gather + hidden_sum init ----------------
__global__ void k_gather(const int* __restrict__ ids,
                         const float* __restrict__ emb, int Nn) {
    int idx = blockIdx.x * blockDim.x + threadIdx.x;
    int row = idx >> 7;
    if (row >= Nn) return;
    int c = (idx & 127) << 2;
    int e = ids[row];
    float4 val = *(const float4*)(emb + (size_t)e * D + c);
    *(float4*)(g_h + (size_t)row * D + c) = val;
    *(float4*)(g_hsum + (size_t)row * D + c) = val;
}

// z = 2*h   ((1+eps)*h with eps=0, plus the self-loop message h)
__global__ void k_scale2(int Nn) {
    int idx = blockIdx.x * blockDim.x + threadIdx.x;
    if (idx >= Nn * 128) return;
    float4 v = *(const float4*)(g_h + (size_t)idx * 4);
    v.x *= 2.f; v.y *= 2.f; v.z *= 2.f; v.w *= 2.f;
    *(float4*)(g_z + (size_t)idx * 4) = v;
}

// undirected edge scatter: z[v]+=h[u], z[u]+=h[v]
__global__ void k_scatter(const int* __restrict__ u, const int* __restrict__ v, int E) {
    int idx = blockIdx.x * blockDim.x + threadIdx.x;
    if (idx >= E * 128) return;
    int e = idx >> 7;
    int c = (idx & 127) << 2;
    int a = __ldg(u + e), b = __ldg(v + e);
    float4 ha = *(const float4*)(g_h + (size_t)a * D + c);
    float4 hb = *(const float4*)(g_h + (size_t)b * D + c);
    float* zb = g_z + (size_t)b * D + c;
    atomicAdd(zb + 0, ha.x); atomicAdd(zb + 1, ha.y);
    atomicAdd(zb + 2, ha.z); atomicAdd(zb + 3, ha.w);
    float* za = g_z + (size_t)a * D + c;
    atomicAdd(za + 0, hb.x); atomicAdd(za + 1, hb.y);
    atomicAdd(za + 2, hb.z); atomicAdd(za + 3, hb.w);
}

// ---------------- tiled SGEMM: C[M,N] = A[M,K] @ B[K,N] ----------------
// GATHER=1: logical A row r = concat(H[gu[r]], H[gv[r]]), K must be 1024, A=H.
// EPI: 0 = plain store, 1 = bias+relu, 2 = bias
template <int GATHER, int EPI>
__global__ __launch_bounds__(256, 2)
void k_sgemm(const float* __restrict__ A, const float* __restrict__ B,
             float* __restrict__ C, int M, int N, int K,
             const int* __restrict__ gu, const int* __restrict__ gv,
             const float* __restrict__ bias) {
    __shared__ __align__(16) float As[8][128];
    __shared__ __align__(16) float Bs[8][128];

    const int bm = blockIdx.x * 128, bn = blockIdx.y * 128;
    const int tid = threadIdx.x;
    const int tx = tid & 15, ty = tid >> 4;

    const int la_r = tid >> 1;          // 0..127
    const int la_c = (tid & 1) * 4;     // 0 or 4
    const int lb_r = tid >> 5;          // 0..7
    const int lb_c = (tid & 31) * 4;

    const int arow = bm + la_r;
    size_t arow_off = 0;
    int gia = 0, gib = 0;
    if (arow < M) {
        if (GATHER) { gia = gu[arow]; gib = gv[arow]; }
        else arow_off = (size_t)arow * K;
    }

    float acc[8][8];
#pragma unroll
    for (int i = 0; i < 8; i++)
#pragma unroll
        for (int j = 0; j < 8; j++) acc[i][j] = 0.f;

    for (int k0 = 0; k0 < K; k0 += 8) {
        float4 av = make_float4(0.f, 0.f, 0.f, 0.f);
        if (arow < M) {
            if (!GATHER) {
                av = *(const float4*)(A + arow_off + k0 + la_c);
            } else {
                int k = k0 + la_c;
                int node = (k < 512) ? gia : gib;
                av = *(const float4*)(A + (size_t)node * 512 + (k & 511));
            }
        }
        As[la_c + 0][la_r] = av.x;
        As[la_c + 1][la_r] = av.y;
        As[la_c + 2][la_r] = av.z;
        As[la_c + 3][la_r] = av.w;

        float4 bv = *(const float4*)(B + (size_t)(k0 + lb_r) * N + bn + lb_c);
        *(float4*)&Bs[lb_r][lb_c] = bv;

        __syncthreads();
#pragma unroll
        for (int kk = 0; kk < 8; kk++) {
            float a[8], b[8];
            *(float4*)(a)     = *(const float4*)&As[kk][ty * 8];
            *(float4*)(a + 4) = *(const float4*)&As[kk][ty * 8 + 4];
            *(float4*)(b)     = *(const float4*)&Bs[kk][tx * 8];
            *(float4*)(b + 4) = *(const float4*)&Bs[kk][tx * 8 + 4];
#pragma unroll
            for (int i = 0; i < 8; i++)
#pragma unroll
                for (int j = 0; j < 8; j++) acc[i][j] += a[i] * b[j];
        }
        __syncthreads();
    }

#pragma unroll
    for (int i = 0; i < 8; i++) {
        int r = bm + ty * 8 + i;
        if (r >= M) break;
#pragma unroll
        for (int j = 0; j < 8; j += 4) {
            int cidx = bn + tx * 8 + j;
            float4 val = make_float4(acc[i][j], acc[i][j + 1], acc[i][j + 2], acc[i][j + 3]);
            if (EPI >= 1) {
                float4 bb = *(const float4*)(bias + cidx);
                val.x += bb.x; val.y += bb.y; val.z += bb.z; val.w += bb.w;
                if (EPI == 1) {
                    val.x = fmaxf(val.x, 0.f); val.y = fmaxf(val.y, 0.f);
                    val.z = fmaxf(val.z, 0.f); val.w = fmaxf(val.w, 0.f);
                }
            }
            *(float4*)(C + (size_t)r * N + cidx) = val;
        }
    }
}

// ---------------- batch-norm helpers ----------------
__global__ void k_bnzero() {
    int t = threadIdx.x;
    if (t < 2 * D) g_stats[t] = 0.f;
}

#define BN_ROWS 256
__global__ void k_bnstats(const float* __restrict__ Y, int M) {
    int col = threadIdx.x;           // 512 threads
    int r0 = blockIdx.x * BN_ROWS;
    int r1 = min(r0 + BN_ROWS, M);
    float s = 0.f, s2 = 0.f;
    for (int r = r0; r < r1; r++) {
        float val = Y[(size_t)r * D + col];
        s += val; s2 += val * val;
    }
    atomicAdd(&g_stats[col], s);
    atomicAdd(&g_stats[D + col], s2);
}

__global__ void k_bnfin(const float* __restrict__ gamma,
                        const float* __restrict__ beta, int M) {
    int j = threadIdx.x;
    if (j >= D) return;
    float inv = 1.f / (float)M;
    float m = g_stats[j] * inv;
    float var = g_stats[D + j] * inv - m * m;
    float sc = gamma[j] * rsqrtf(var + BN_EPS);
    g_aff[j] = sc;
    g_aff[D + j] = beta[j] - m * sc;
}

// in-place: Y = relu(Y*scale + shift)
__global__ void k_bnrelu(float* __restrict__ Y, int Nn) {
    int idx = blockIdx.x * blockDim.x + threadIdx.x;
    if (idx >= Nn * 128) return;
    int c = (idx & 127) << 2;
    float4 v = *(const float4*)(Y + (size_t)idx * 4);
    v.x = fmaxf(v.x * g_aff[c + 0] + g_aff[D + c + 0], 0.f);
    v.y = fmaxf(v.y * g_aff[c + 1] + g_aff[D + c + 1], 0.f);
    v.z = fmaxf(v.z * g_aff[c + 2] + g_aff[D + c + 2], 0.f);
    v.w = fmaxf(v.w * g_aff[c + 3] + g_aff[D + c + 3], 0.f);
    *(float4*)(Y + (size_t)idx * 4) = v;
}

// h = relu(Y2*scale+shift); hsum += h
__global__ void k_bnrelu_acc(const float* __restrict__ Y2, int Nn) {
    int idx = blockIdx.x * blockDim.x + threadIdx.x;
    if (idx >= Nn * 128) return;
    int c = (idx & 127) << 2;
    float4 v = *(const float4*)(Y2 + (size_t)idx * 4);
    v.x = fmaxf(v.x * g_aff[c + 0] + g_aff[D + c + 0], 0.f);
    v.y = fmaxf(v.y * g_aff[c + 1] + g_aff[D + c + 1], 0.f);
    v.z = fmaxf(v.z * g_aff[c + 2] + g_aff[D + c + 2], 0.f);
    v.w = fmaxf(v.w * g_aff[c + 3] + g_aff[D + c + 3], 0.f);
    *(float4*)(g_h + (size_t)idx * 4) = v;
    float4 hs = *(const float4*)(g_hsum + (size_t)idx * 4);
    hs.x += v.x; hs.y += v.y; hs.z += v.z; hs.w += v.w;
    *(float4*)(g_hsum + (size_t)idx * 4) = hs;
}

// ---------------- launch ----------------
extern "C" void kernel_launch(void* const* d_in, const int* in_sizes, int n_in,
                              void* d_out, int out_size) {
    const int* h_ids = (const int*)d_in[0];
    const int* u     = (const int*)d_in[1];
    const int* v     = (const int*)d_in[2];
    const float* emb   = (const float*)d_in[3];
    const float* lin1  = (const float*)d_in[4];
    const float* lin2  = (const float*)d_in[5];
    const float* bn1_g = (const float*)d_in[6];
    const float* bn1_b = (const float*)d_in[7];
    const float* bn2_g = (const float*)d_in[8];
    const float* bn2_b = (const float*)d_in[9];
    const float* W1_w  = (const float*)d_in[10];
    const float* W1_b  = (const float*)d_in[11];
    const float* W2_w  = (const float*)d_in[12];
    const float* W2_b  = (const float*)d_in[13];
    float* out = (float*)d_out;

    const int N = in_sizes[0];
    const int E = in_sizes[1];
    const int L = in_sizes[4] / (D * D);

    float *dg_h, *dg_hsum, *dg_z, *dg_y, *dg_s1;
    cudaGetSymbolAddress((void**)&dg_h, g_h);
    cudaGetSymbolAddress((void**)&dg_hsum, g_hsum);
    cudaGetSymbolAddress((void**)&dg_z, g_z);
    cudaGetSymbolAddress((void**)&dg_y, g_y);
    cudaGetSymbolAddress((void**)&dg_s1, g_s1);

    const int ew = N * 128;                 // float4 work items over [N, D]
    const int ewB = (ew + 255) / 256;
    const int sc = E * 128;
    const int scB = (sc + 255) / 256;
    const int mtiles = (N + 127) / 128;
    const int etiles = (E + 127) / 128;
    const int bnB = (N + BN_ROWS - 1) / BN_ROWS;

    // h = emb[h_ids]; hidden_sum = h
    k_gather<<<ewB, 256>>>(h_ids, emb, N);

    for (int i = 0; i < L; i++) {
        // z = 2h + neighbor sums
        k_scale2<<<ewB, 256>>>(N);
        k_scatter<<<scB, 256>>>(u, v, E);
        // y = z @ lin1[i]
        k_sgemm<0, 0><<<dim3(mtiles, D / 128), 256>>>(
            dg_z, lin1 + (size_t)i * D * D, dg_y, N, D, D, nullptr, nullptr, nullptr);
        // BN1 + relu
        k_bnzero<<<1, 1024>>>();
        k_bnstats<<<bnB, D>>>(dg_y, N);
        k_bnfin<<<1, D>>>(bn1_g + (size_t)i * D, bn1_b + (size_t)i * D, N);
        k_bnrelu<<<ewB, 256>>>(dg_y, N);
        // z(out) = y @ lin2[i]
        k_sgemm<0, 0><<<dim3(mtiles, D / 128), 256>>>(
            dg_y, lin2 + (size_t)i * D * D, dg_z, N, D, D, nullptr, nullptr, nullptr);
        // BN2 + relu, h update, hidden_sum accumulate
        k_bnzero<<<1, 1024>>>();
        k_bnstats<<<bnB, D>>>(dg_z, N);
        k_bnfin<<<1, D>>>(bn2_g + (size_t)i * D, bn2_b + (size_t)i * D, N);
        k_bnrelu_acc<<<ewB, 256>>>(dg_z, N);
    }

    // decoder: s1 = relu(concat(H[u],H[v]) @ W1 + b1)   [E, 512]
    k_sgemm<1, 1><<<dim3(etiles, D / 128), 256>>>(
        dg_hsum, W1_w, dg_s1, E, D, 2 * D, u, v, W1_b);
    // out = s1 @ W2 + b2                                 [E, 128]
    k_sgemm<0, 2><<<dim3(etiles, 1), 256>>>(
        dg_s1, W2_w, out, E, OUTD, D, nullptr, nullptr, W2_b);
}